// round 15
// baseline (speedup 1.0000x reference)
#include <cuda_runtime.h>
#include <cuda_fp16.h>
#include <cstdint>

// Problem constants
#define BB      16
#define NC      1024
#define NF      4096
#define M_FINE  (BB * NF)       // 65536
#define CIN     256
#define CSKIP   128
#define C0      384
#define HID     512

// ---------------------------------------------------------------------------
// Device scratch (no cudaMalloc allowed)
// ---------------------------------------------------------------------------
__device__ __half g_xi[(size_t)M_FINE * C0];     // fp16 activations (layer-1 input)
__device__ __half g_h1[(size_t)M_FINE * HID];    // fp16 hidden (layer-2 input)
__device__ __half g_wt1[HID * C0];               // [n][k] = w1[k][n], fp16
__device__ __half g_wt2[HID * HID];
__device__ int   g_knn_idx[M_FINE * 3];
__device__ float g_knn_w[M_FINE * 3];

// ---------------------------------------------------------------------------
// Baseline-ISA tensor-core helpers (valid in compute_103 PTX)
// ---------------------------------------------------------------------------
__device__ __forceinline__ uint32_t smem_to_u32(const void* p) {
    uint32_t a;
    asm("{ .reg .u64 t; cvta.to.shared.u64 t, %1; cvt.u32.u64 %0, t; }" : "=r"(a) : "l"(p));
    return a;
}
__device__ __forceinline__ void cp_async16(uint32_t saddr, const void* gaddr) {
    asm volatile("cp.async.cg.shared.global [%0], [%1], 16;" :: "r"(saddr), "l"(gaddr));
}
#define CP_COMMIT() asm volatile("cp.async.commit_group;" ::: "memory")
#define CP_WAIT(N)  asm volatile("cp.async.wait_group %0;" :: "n"(N) : "memory")

__device__ __forceinline__ void ldsm_x4(uint32_t* r, uint32_t addr) {
    asm volatile("ldmatrix.sync.aligned.m8n8.x4.shared.b16 {%0,%1,%2,%3}, [%4];"
                 : "=r"(r[0]), "=r"(r[1]), "=r"(r[2]), "=r"(r[3]) : "r"(addr));
}
__device__ __forceinline__ void mma_fp16(float* c, const uint32_t* a, const uint32_t* b) {
    asm volatile("mma.sync.aligned.m16n8k16.row.col.f32.f16.f16.f32 "
                 "{%0,%1,%2,%3}, {%4,%5,%6,%7}, {%8,%9}, {%0,%1,%2,%3};"
                 : "+f"(c[0]), "+f"(c[1]), "+f"(c[2]), "+f"(c[3])
                 : "r"(a[0]), "r"(a[1]), "r"(a[2]), "r"(a[3]), "r"(b[0]), "r"(b[1]));
}

// ---------------------------------------------------------------------------
// Weight prep: smem-tiled transpose + fp16 convert (coalesced both ways)
// ---------------------------------------------------------------------------
#define W1_TILES ((C0 / 32) * (HID / 32))    // 192
#define W2_TILES ((HID / 32) * (HID / 32))   // 256
__global__ void wprep_kernel(const float* __restrict__ w1, const float* __restrict__ w2) {
    __shared__ float tile[32][33];
    int bt = blockIdx.x;
    const float* w;
    __half* dh;
    int KD;
    if (bt < W1_TILES) { w = w1; dh = g_wt1; KD = C0; }
    else { bt -= W1_TILES; w = w2; dh = g_wt2; KD = HID; }
    const int tk = bt / (HID / 32);
    const int tn = bt % (HID / 32);
    const int c  = threadIdx.x & 31;
    const int r0 = threadIdx.x >> 5;      // 0..7
#pragma unroll
    for (int rr = 0; rr < 32; rr += 8)
        tile[r0 + rr][c] = w[(size_t)(tk * 32 + r0 + rr) * HID + tn * 32 + c];
    __syncthreads();
#pragma unroll
    for (int rr = 0; rr < 32; rr += 8) {
        const int n = tn * 32 + r0 + rr;
        const int k = tk * 32 + c;
        dh[(size_t)n * KD + k] = __float2half(tile[c][r0 + rr]);   // = w[k][n]
    }
}

// ---------------------------------------------------------------------------
// Kernel 1: brute-force kNN (K=3), TWO query points per thread.
// Each sp[j] smem load is reused for both points -> half the LDS traffic.
// grid = (BB, NF/512), block = 256
// ---------------------------------------------------------------------------
__global__ void knn_kernel(const float* __restrict__ pos,
                           const float* __restrict__ pos_skip) {
    __shared__ float sp[NC * 3];
    const int b = blockIdx.x;
    const float* pbase = pos + (size_t)b * NC * 3;
    for (int i = threadIdx.x; i < NC * 3; i += blockDim.x) sp[i] = pbase[i];
    __syncthreads();

    const int pA = b * NF + blockIdx.y * 512 + threadIdx.x;
    const int pB = pA + 256;
    const float qAx = pos_skip[(size_t)pA * 3 + 0];
    const float qAy = pos_skip[(size_t)pA * 3 + 1];
    const float qAz = pos_skip[(size_t)pA * 3 + 2];
    const float qBx = pos_skip[(size_t)pB * 3 + 0];
    const float qBy = pos_skip[(size_t)pB * 3 + 1];
    const float qBz = pos_skip[(size_t)pB * 3 + 2];

    float a0 = 1e30f, a1 = 1e30f, a2 = 1e30f;
    int   ia0 = 0,    ia1 = 0,    ia2 = 0;
    float b0 = 1e30f, b1 = 1e30f, b2 = 1e30f;
    int   ib0 = 0,    ib1 = 0,    ib2 = 0;

#pragma unroll 4
    for (int j = 0; j < NC; j++) {
        const float px = sp[j * 3 + 0];
        const float py = sp[j * 3 + 1];
        const float pz = sp[j * 3 + 2];
        {
            const float dx = qAx - px, dy = qAy - py, dz = qAz - pz;
            const float d = dx * dx + dy * dy + dz * dz;
            if (d < a2) {
                if (d < a1) {
                    a2 = a1; ia2 = ia1;
                    if (d < a0) { a1 = a0; ia1 = ia0; a0 = d; ia0 = j; }
                    else        { a1 = d;  ia1 = j; }
                } else { a2 = d; ia2 = j; }
            }
        }
        {
            const float dx = qBx - px, dy = qBy - py, dz = qBz - pz;
            const float d = dx * dx + dy * dy + dz * dz;
            if (d < b2) {
                if (d < b1) {
                    b2 = b1; ib2 = ib1;
                    if (d < b0) { b1 = b0; ib1 = ib0; b0 = d; ib0 = j; }
                    else        { b1 = d;  ib1 = j; }
                } else { b2 = d; ib2 = j; }
            }
        }
    }

    {
        const float w0 = 1.0f / fmaxf(a0, 1e-16f);
        const float w1 = 1.0f / fmaxf(a1, 1e-16f);
        const float w2 = 1.0f / fmaxf(a2, 1e-16f);
        const float inv = 1.0f / (w0 + w1 + w2);
        g_knn_idx[pA * 3 + 0] = b * NC + ia0;
        g_knn_idx[pA * 3 + 1] = b * NC + ia1;
        g_knn_idx[pA * 3 + 2] = b * NC + ia2;
        g_knn_w  [pA * 3 + 0] = w0 * inv;
        g_knn_w  [pA * 3 + 1] = w1 * inv;
        g_knn_w  [pA * 3 + 2] = w2 * inv;
    }
    {
        const float w0 = 1.0f / fmaxf(b0, 1e-16f);
        const float w1 = 1.0f / fmaxf(b1, 1e-16f);
        const float w2 = 1.0f / fmaxf(b2, 1e-16f);
        const float inv = 1.0f / (w0 + w1 + w2);
        g_knn_idx[pB * 3 + 0] = b * NC + ib0;
        g_knn_idx[pB * 3 + 1] = b * NC + ib1;
        g_knn_idx[pB * 3 + 2] = b * NC + ib2;
        g_knn_w  [pB * 3 + 0] = w0 * inv;
        g_knn_w  [pB * 3 + 1] = w1 * inv;
        g_knn_w  [pB * 3 + 2] = w2 * inv;
    }
}

// ---------------------------------------------------------------------------
// Kernel 2: gather + interpolate + concat -> fp16 [M, 384]  (R8 form)
// ---------------------------------------------------------------------------
__global__ void gather_kernel(const float* __restrict__ x,
                              const float* __restrict__ x_skip) {
    const int p = blockIdx.x;
    const int t = threadIdx.x;       // 128 threads
    const int   i0 = g_knn_idx[p * 3 + 0];
    const int   i1 = g_knn_idx[p * 3 + 1];
    const int   i2 = g_knn_idx[p * 3 + 2];
    const float w0 = g_knn_w[p * 3 + 0];
    const float w1 = g_knn_w[p * 3 + 1];
    const float w2 = g_knn_w[p * 3 + 2];

    const float2* r0 = (const float2*)(x + (size_t)i0 * CIN);
    const float2* r1 = (const float2*)(x + (size_t)i1 * CIN);
    const float2* r2 = (const float2*)(x + (size_t)i2 * CIN);
    __half* out = g_xi + (size_t)p * C0;
    {
        const float2 a = r0[t], b = r1[t], c = r2[t];
        const float v0 = w0 * a.x + w1 * b.x + w2 * c.x;
        const float v1 = w0 * a.y + w1 * b.y + w2 * c.y;
        *(__half2*)(out + 2 * t) = __floats2half2_rn(v0, v1);
    }
    out[CIN + t] = __float2half(x_skip[(size_t)p * CSKIP + t]);
}

// ---------------------------------------------------------------------------
// Kernel 3: fp16 HMMA GEMM, single-term fp16 weights.  (R8 configuration)
// CTA tile 128x256, 512 threads = 16 warps (2m x 8n), warp 64x32, K-step 64.
// 3-stage cp.async pipeline (2 tiles ahead, wait 1), ONE __syncthreads/K-tile.
// ---------------------------------------------------------------------------
#define RSTRIDE   144                         // 64 halves + 8 pad
#define A_TILE_B  (128 * RSTRIDE)             // 18432 B
#define W_TILE_B  (256 * RSTRIDE)             // 36864 B
#define STAGE_B   (A_TILE_B + W_TILE_B)       // 55296 B
#define NSTAGE    3
#define SMEM_GEMM (NSTAGE * STAGE_B)          // 165888 B -> 1 CTA/SM (16 warps)

template <int KD, int OUT_HALF>
__global__ void __launch_bounds__(512, 1)
gemm_mma(const __half* __restrict__ A, const __half* __restrict__ W,
         const float* __restrict__ bias, const float* __restrict__ gam,
         const float* __restrict__ bet,  const float* __restrict__ mu,
         const float* __restrict__ var,
         float* __restrict__ Cf, __half* __restrict__ Ch) {
    extern __shared__ char smem[];
    const uint32_t sbase = smem_to_u32(smem);
    const int tid  = threadIdx.x;
    const int wid  = tid >> 5, lane = tid & 31;
    const int wm   = wid >> 3;          // 0..1  (64-row slab)
    const int wn   = wid & 7;           // 0..7  (32-col slab)
    const int bm0  = blockIdx.y * 128;
    const int bn0  = blockIdx.x * 256;

    const int arow  = tid >> 2;                // 0..127
    const int aseg0 = (tid & 3) * 2;           // 0,2,4,6
    const int wrow  = tid >> 1;                // 0..255
    const int wseg0 = (tid & 1) * 4;           // 0 or 4

    auto load_stage = [&](int kt) {
        const int k0 = kt * 64;
        const uint32_t stg = sbase + (kt % NSTAGE) * STAGE_B;
        const size_t ga = (size_t)(bm0 + arow) * KD + k0 + aseg0 * 8;
        const uint32_t sa = arow * RSTRIDE + aseg0 * 16;
#pragma unroll
        for (int s = 0; s < 2; s++)
            cp_async16(stg + sa + s * 16, A + ga + s * 8);
        const size_t gw = (size_t)(bn0 + wrow) * KD + k0 + wseg0 * 8;
        const uint32_t sw = A_TILE_B + wrow * RSTRIDE + wseg0 * 16;
#pragma unroll
        for (int s = 0; s < 4; s++)
            cp_async16(stg + sw + s * 16, W + gw + s * 8);
    };

    float acc[4][4][4] = {};   // [mi][ni][frag]

    const uint32_t a_row  = wm * 64 + (lane & 15);
    const uint32_t a_colb = (lane >> 4) * 16;
    const uint32_t b_row  = wn * 32 + ((lane >> 4) << 3) + (lane & 7);
    const uint32_t b_colb = ((lane >> 3) & 1) * 16;

    load_stage(0); CP_COMMIT();
    load_stage(1); CP_COMMIT();

    constexpr int NT = KD / 64;
#pragma unroll 1
    for (int t = 0; t < NT; t++) {
        CP_WAIT(1);
        __syncthreads();                     // single barrier per K-tile
        if (t + 2 < NT) { load_stage(t + 2); CP_COMMIT(); }

        const uint32_t stg = sbase + (t % NSTAGE) * STAGE_B;
        const uint32_t a_base = stg;
        const uint32_t w_base = stg + A_TILE_B;

#pragma unroll
        for (int kf = 0; kf < 4; kf++) {
            uint32_t af[4][4], bf[2][4];
#pragma unroll
            for (int mi = 0; mi < 4; mi++)
                ldsm_x4(af[mi], a_base + (a_row + mi * 16) * RSTRIDE + kf * 32 + a_colb);
#pragma unroll
            for (int nb = 0; nb < 2; nb++)
                ldsm_x4(bf[nb], w_base + (b_row + nb * 16) * RSTRIDE + kf * 32 + b_colb);
#pragma unroll
            for (int mi = 0; mi < 4; mi++)
#pragma unroll
                for (int nb = 0; nb < 2; nb++) {
                    mma_fp16(acc[mi][2 * nb + 0], af[mi], bf[nb] + 0);
                    mma_fp16(acc[mi][2 * nb + 1], af[mi], bf[nb] + 2);
                }
        }
        // no trailing barrier: next iteration's barrier protects stage reuse
    }

    // ----- fused epilogue: bias -> ReLU -> BN -----
#pragma unroll
    for (int ni = 0; ni < 4; ni++) {
        const int c0 = bn0 + wn * 32 + ni * 8 + (lane & 3) * 2;
        const float sa = gam[c0]     * rsqrtf(var[c0]     + 1e-5f);
        const float sb = gam[c0 + 1] * rsqrtf(var[c0 + 1] + 1e-5f);
        const float sh0 = bet[c0]     - mu[c0]     * sa;
        const float sh1 = bet[c0 + 1] - mu[c0 + 1] * sb;
        const float bb0 = bias[c0], bb1 = bias[c0 + 1];
#pragma unroll
        for (int mi = 0; mi < 4; mi++) {
#pragma unroll
            for (int half = 0; half < 2; half++) {
                const int row = bm0 + wm * 64 + mi * 16 + (lane >> 2) + half * 8;
                const float v0 = fmaf(fmaxf(acc[mi][ni][half * 2 + 0] + bb0, 0.0f), sa, sh0);
                const float v1 = fmaf(fmaxf(acc[mi][ni][half * 2 + 1] + bb1, 0.0f), sb, sh1);
                if (OUT_HALF) {
                    *(__half2*)(Ch + (size_t)row * HID + c0) = __floats2half2_rn(v0, v1);
                } else {
                    float2 o; o.x = v0; o.y = v1;
                    *(float2*)(Cf + (size_t)row * HID + c0) = o;
                }
            }
        }
    }
}

// ---------------------------------------------------------------------------
// Optional tail (pos_skip / batch_skip passthrough)
// ---------------------------------------------------------------------------
__global__ void tail_kernel(const float* __restrict__ pos_skip, float* __restrict__ out,
                            int has_pos, int has_batch) {
    const int i = blockIdx.x * blockDim.x + threadIdx.x;
    size_t off = (size_t)M_FINE * HID;
    if (has_pos) {
        if (i < M_FINE * 3) out[off + i] = pos_skip[i];
        off += (size_t)M_FINE * 3;
    }
    if (has_batch) {
        if (i < M_FINE) out[off + i] = (float)(i / NF);
    }
}

// ---------------------------------------------------------------------------
extern "C" void kernel_launch(void* const* d_in, const int* in_sizes, int n_in,
                              void* d_out, int out_size) {
    const float* x        = (const float*)d_in[0];
    const float* pos      = (const float*)d_in[1];
    const float* x_skip   = (const float*)d_in[3];
    const float* pos_skip = (const float*)d_in[4];
    const float* w1  = (const float*)d_in[6];
    const float* b1  = (const float*)d_in[7];
    const float* g1  = (const float*)d_in[8];
    const float* be1 = (const float*)d_in[9];
    const float* m1  = (const float*)d_in[10];
    const float* v1  = (const float*)d_in[11];
    const float* w2  = (const float*)d_in[12];
    const float* b2  = (const float*)d_in[13];
    const float* g2  = (const float*)d_in[14];
    const float* be2 = (const float*)d_in[15];
    const float* m2  = (const float*)d_in[16];
    const float* v2  = (const float*)d_in[17];
    float* out = (float*)d_out;

    static __half *xi = nullptr, *h1, *wt1, *wt2;
    if (!xi) {
        cudaGetSymbolAddress((void**)&xi, g_xi);
        cudaGetSymbolAddress((void**)&h1, g_h1);
        cudaGetSymbolAddress((void**)&wt1, g_wt1);
        cudaGetSymbolAddress((void**)&wt2, g_wt2);
        cudaFuncSetAttribute(gemm_mma<C0, 1>,  cudaFuncAttributeMaxDynamicSharedMemorySize, SMEM_GEMM);
        cudaFuncSetAttribute(gemm_mma<HID, 0>, cudaFuncAttributeMaxDynamicSharedMemorySize, SMEM_GEMM);
    }

    // 0) weight prep (tiled transpose + fp16 convert)
    wprep_kernel<<<W1_TILES + W2_TILES, 256>>>(w1, w2);
    // 1) kNN (2 points per thread)
    knn_kernel<<<dim3(BB, NF / 512), 256>>>(pos, pos_skip);
    // 2) interpolate + concat (fp16)
    gather_kernel<<<M_FINE, 128>>>(x, x_skip);
    // 3) MLP block 1: [M,384] @ [384,512] -> h1 (fp16)
    gemm_mma<C0, 1><<<dim3(HID / 256, M_FINE / 128), 512, SMEM_GEMM>>>(
        xi, wt1, b1, g1, be1, m1, v1, nullptr, h1);
    // 4) MLP block 2: [M,512] @ [512,512] -> d_out (fp32)
    gemm_mma<HID, 0><<<dim3(HID / 256, M_FINE / 128), 512, SMEM_GEMM>>>(
        h1, wt2, b2, g2, be2, m2, v2, out, nullptr);

    // 5) optional passthrough outputs
    const long extra = (long)out_size - (long)M_FINE * HID;
    if (extra > 0) {
        const int has_pos   = (extra >= (long)M_FINE * 3) ? 1 : 0;
        const long rem      = extra - (has_pos ? (long)M_FINE * 3 : 0);
        const int has_batch = (rem >= (long)M_FINE) ? 1 : 0;
        const int nmax = has_pos ? M_FINE * 3 : M_FINE;
        tail_kernel<<<(nmax + 255) / 256, 256>>>(pos_skip, out, has_pos, has_batch);
    }
}

// round 16
// speedup vs baseline: 1.0628x; 1.0628x over previous
#include <cuda_runtime.h>
#include <cuda_fp16.h>
#include <cstdint>

// Problem constants
#define BB      16
#define NC      1024
#define NF      4096
#define M_FINE  (BB * NF)       // 65536
#define CIN     256
#define CSKIP   128
#define C0      384
#define HID     512

// ---------------------------------------------------------------------------
// Device scratch (no cudaMalloc allowed)
// ---------------------------------------------------------------------------
__device__ __half g_xi[(size_t)M_FINE * C0];     // fp16 activations (layer-1 input)
__device__ __half g_h1[(size_t)M_FINE * HID];    // fp16 hidden (layer-2 input)
__device__ __half g_wt1[HID * C0];               // [n][k] = w1[k][n], fp16
__device__ __half g_wt2[HID * HID];
__device__ int   g_knn_idx[M_FINE * 3];
__device__ float g_knn_w[M_FINE * 3];

// ---------------------------------------------------------------------------
// Baseline-ISA tensor-core helpers (valid in compute_103 PTX)
// ---------------------------------------------------------------------------
__device__ __forceinline__ uint32_t smem_to_u32(const void* p) {
    uint32_t a;
    asm("{ .reg .u64 t; cvta.to.shared.u64 t, %1; cvt.u32.u64 %0, t; }" : "=r"(a) : "l"(p));
    return a;
}
__device__ __forceinline__ void cp_async16(uint32_t saddr, const void* gaddr) {
    asm volatile("cp.async.cg.shared.global [%0], [%1], 16;" :: "r"(saddr), "l"(gaddr));
}
#define CP_COMMIT() asm volatile("cp.async.commit_group;" ::: "memory")
#define CP_WAIT(N)  asm volatile("cp.async.wait_group %0;" :: "n"(N) : "memory")

__device__ __forceinline__ void ldsm_x4(uint32_t* r, uint32_t addr) {
    asm volatile("ldmatrix.sync.aligned.m8n8.x4.shared.b16 {%0,%1,%2,%3}, [%4];"
                 : "=r"(r[0]), "=r"(r[1]), "=r"(r[2]), "=r"(r[3]) : "r"(addr));
}
__device__ __forceinline__ void mma_fp16(float* c, const uint32_t* a, const uint32_t* b) {
    asm volatile("mma.sync.aligned.m16n8k16.row.col.f32.f16.f16.f32 "
                 "{%0,%1,%2,%3}, {%4,%5,%6,%7}, {%8,%9}, {%0,%1,%2,%3};"
                 : "+f"(c[0]), "+f"(c[1]), "+f"(c[2]), "+f"(c[3])
                 : "r"(a[0]), "r"(a[1]), "r"(a[2]), "r"(a[3]), "r"(b[0]), "r"(b[1]));
}

// ---------------------------------------------------------------------------
// Weight prep: smem-tiled transpose + fp16 convert (coalesced both ways)
// ---------------------------------------------------------------------------
#define W1_TILES ((C0 / 32) * (HID / 32))    // 192
#define W2_TILES ((HID / 32) * (HID / 32))   // 256
__global__ void wprep_kernel(const float* __restrict__ w1, const float* __restrict__ w2) {
    __shared__ float tile[32][33];
    int bt = blockIdx.x;
    const float* w;
    __half* dh;
    int KD;
    if (bt < W1_TILES) { w = w1; dh = g_wt1; KD = C0; }
    else { bt -= W1_TILES; w = w2; dh = g_wt2; KD = HID; }
    const int tk = bt / (HID / 32);
    const int tn = bt % (HID / 32);
    const int c  = threadIdx.x & 31;
    const int r0 = threadIdx.x >> 5;      // 0..7
#pragma unroll
    for (int rr = 0; rr < 32; rr += 8)
        tile[r0 + rr][c] = w[(size_t)(tk * 32 + r0 + rr) * HID + tn * 32 + c];
    __syncthreads();
#pragma unroll
    for (int rr = 0; rr < 32; rr += 8) {
        const int n = tn * 32 + r0 + rr;
        const int k = tk * 32 + c;
        dh[(size_t)n * KD + k] = __float2half(tile[c][r0 + rr]);   // = w[k][n]
    }
}

// ---------------------------------------------------------------------------
// Kernel 1: brute-force kNN (K=3)
// ---------------------------------------------------------------------------
__global__ void knn_kernel(const float* __restrict__ pos,
                           const float* __restrict__ pos_skip) {
    __shared__ float sp[NC * 3];
    const int b = blockIdx.x;
    const float* pbase = pos + (size_t)b * NC * 3;
    for (int i = threadIdx.x; i < NC * 3; i += blockDim.x) sp[i] = pbase[i];
    __syncthreads();

    const int p = b * NF + blockIdx.y * blockDim.x + threadIdx.x;
    const float qx = pos_skip[(size_t)p * 3 + 0];
    const float qy = pos_skip[(size_t)p * 3 + 1];
    const float qz = pos_skip[(size_t)p * 3 + 2];

    float d0 = 1e30f, d1 = 1e30f, d2 = 1e30f;
    int   i0 = 0,     i1 = 0,     i2 = 0;
#pragma unroll 4
    for (int j = 0; j < NC; j++) {
        const float dx = qx - sp[j * 3 + 0];
        const float dy = qy - sp[j * 3 + 1];
        const float dz = qz - sp[j * 3 + 2];
        const float d  = dx * dx + dy * dy + dz * dz;
        if (d < d2) {
            if (d < d1) {
                d2 = d1; i2 = i1;
                if (d < d0) { d1 = d0; i1 = i0; d0 = d; i0 = j; }
                else        { d1 = d;  i1 = j; }
            } else { d2 = d; i2 = j; }
        }
    }
    const float w0 = 1.0f / fmaxf(d0, 1e-16f);
    const float w1 = 1.0f / fmaxf(d1, 1e-16f);
    const float w2 = 1.0f / fmaxf(d2, 1e-16f);
    const float inv = 1.0f / (w0 + w1 + w2);
    g_knn_idx[p * 3 + 0] = b * NC + i0;
    g_knn_idx[p * 3 + 1] = b * NC + i1;
    g_knn_idx[p * 3 + 2] = b * NC + i2;
    g_knn_w  [p * 3 + 0] = w0 * inv;
    g_knn_w  [p * 3 + 1] = w1 * inv;
    g_knn_w  [p * 3 + 2] = w2 * inv;
}

// ---------------------------------------------------------------------------
// Kernel 2: gather + interpolate + concat -> fp16 [M, 384]
// ---------------------------------------------------------------------------
__global__ void gather_kernel(const float* __restrict__ x,
                              const float* __restrict__ x_skip) {
    const int p = blockIdx.x;
    const int t = threadIdx.x;       // 128 threads
    const int   i0 = g_knn_idx[p * 3 + 0];
    const int   i1 = g_knn_idx[p * 3 + 1];
    const int   i2 = g_knn_idx[p * 3 + 2];
    const float w0 = g_knn_w[p * 3 + 0];
    const float w1 = g_knn_w[p * 3 + 1];
    const float w2 = g_knn_w[p * 3 + 2];

    const float2* r0 = (const float2*)(x + (size_t)i0 * CIN);
    const float2* r1 = (const float2*)(x + (size_t)i1 * CIN);
    const float2* r2 = (const float2*)(x + (size_t)i2 * CIN);
    __half* out = g_xi + (size_t)p * C0;
    {
        const float2 a = r0[t], b = r1[t], c = r2[t];
        const float v0 = w0 * a.x + w1 * b.x + w2 * c.x;
        const float v1 = w0 * a.y + w1 * b.y + w2 * c.y;
        *(__half2*)(out + 2 * t) = __floats2half2_rn(v0, v1);
    }
    out[CIN + t] = __float2half(x_skip[(size_t)p * CSKIP + t]);
}

// ---------------------------------------------------------------------------
// Kernel 3: fp16 HMMA GEMM, single-term fp16 weights.
// CTA tile 128x256, 512 threads = 16 warps (2m x 8n), warp 64x32, K-step 64.
// 3-stage cp.async pipeline, ONE __syncthreads per K-tile.
// 144B-padded rows (conflict-free ldmatrix).
// Fused bias + ReLU + BN. OUT_HALF: emit fp16 for next layer.
// ---------------------------------------------------------------------------
#define RSTRIDE   144                         // 64 halves + 8 pad
#define A_TILE_B  (128 * RSTRIDE)             // 18432 B
#define W_TILE_B  (256 * RSTRIDE)             // 36864 B
#define STAGE_B   (A_TILE_B + W_TILE_B)       // 55296 B
#define NSTAGE    3
#define SMEM_GEMM (NSTAGE * STAGE_B)          // 165888 B -> 1 CTA/SM (16 warps)

template <int KD, int OUT_HALF>
__global__ void __launch_bounds__(512, 1)
gemm_mma(const __half* __restrict__ A, const __half* __restrict__ W,
         const float* __restrict__ bias, const float* __restrict__ gam,
         const float* __restrict__ bet,  const float* __restrict__ mu,
         const float* __restrict__ var,
         float* __restrict__ Cf, __half* __restrict__ Ch) {
    extern __shared__ char smem[];
    const uint32_t sbase = smem_to_u32(smem);
    const int tid  = threadIdx.x;
    const int wid  = tid >> 5, lane = tid & 31;
    const int wm   = wid >> 3;          // 0..1  (64-row slab)
    const int wn   = wid & 7;           // 0..7  (32-col slab)
    const int bm0  = blockIdx.y * 128;
    const int bn0  = blockIdx.x * 256;

    // cp.async mapping (512 threads):
    // A tile: 128 rows x 8 chunks = 1024 chunks -> 2 per thread
    const int arow  = tid >> 2;                // 0..127
    const int aseg0 = (tid & 3) * 2;           // 0,2,4,6
    // W tile: 256 rows x 8 chunks = 2048 chunks -> 4 per thread
    const int wrow  = tid >> 1;                // 0..255
    const int wseg0 = (tid & 1) * 4;           // 0 or 4

    auto load_stage = [&](int kt) {
        const int k0 = kt * 64;
        const uint32_t stg = sbase + (kt % NSTAGE) * STAGE_B;
        const size_t ga = (size_t)(bm0 + arow) * KD + k0 + aseg0 * 8;
        const uint32_t sa = arow * RSTRIDE + aseg0 * 16;
#pragma unroll
        for (int s = 0; s < 2; s++)
            cp_async16(stg + sa + s * 16, A + ga + s * 8);
        const size_t gw = (size_t)(bn0 + wrow) * KD + k0 + wseg0 * 8;
        const uint32_t sw = A_TILE_B + wrow * RSTRIDE + wseg0 * 16;
#pragma unroll
        for (int s = 0; s < 4; s++)
            cp_async16(stg + sw + s * 16, W + gw + s * 8);
    };

    float acc[4][4][4] = {};   // [mi][ni][frag]

    const uint32_t a_row  = wm * 64 + (lane & 15);
    const uint32_t a_colb = (lane >> 4) * 16;
    // B x4 ldmatrix loads two n8 frags: rows wn*32 + nb*16 + (lane>>4)*8 + (lane&7)
    const uint32_t b_row  = wn * 32 + ((lane >> 4) << 3) + (lane & 7);
    const uint32_t b_colb = ((lane >> 3) & 1) * 16;

    load_stage(0); CP_COMMIT();
    load_stage(1); CP_COMMIT();

    constexpr int NT = KD / 64;
#pragma unroll 1
    for (int t = 0; t < NT; t++) {
        CP_WAIT(1);
        __syncthreads();                     // single barrier per K-tile
        if (t + 2 < NT) { load_stage(t + 2); CP_COMMIT(); }

        const uint32_t stg = sbase + (t % NSTAGE) * STAGE_B;
        const uint32_t a_base = stg;
        const uint32_t w_base = stg + A_TILE_B;

#pragma unroll
        for (int kf = 0; kf < 4; kf++) {
            uint32_t af[4][4], bf[2][4];
#pragma unroll
            for (int mi = 0; mi < 4; mi++)
                ldsm_x4(af[mi], a_base + (a_row + mi * 16) * RSTRIDE + kf * 32 + a_colb);
#pragma unroll
            for (int nb = 0; nb < 2; nb++)
                ldsm_x4(bf[nb], w_base + (b_row + nb * 16) * RSTRIDE + kf * 32 + b_colb);
#pragma unroll
            for (int mi = 0; mi < 4; mi++)
#pragma unroll
                for (int nb = 0; nb < 2; nb++) {
                    mma_fp16(acc[mi][2 * nb + 0], af[mi], bf[nb] + 0);
                    mma_fp16(acc[mi][2 * nb + 1], af[mi], bf[nb] + 2);
                }
        }
        // no trailing barrier: next iteration's barrier (after CP_WAIT) protects
        // stage reuse because loads are issued only after that barrier.
    }

    // ----- fused epilogue: bias -> ReLU -> BN -----
#pragma unroll
    for (int ni = 0; ni < 4; ni++) {
        const int c0 = bn0 + wn * 32 + ni * 8 + (lane & 3) * 2;
        const float sa = gam[c0]     * rsqrtf(var[c0]     + 1e-5f);
        const float sb = gam[c0 + 1] * rsqrtf(var[c0 + 1] + 1e-5f);
        const float sh0 = bet[c0]     - mu[c0]     * sa;
        const float sh1 = bet[c0 + 1] - mu[c0 + 1] * sb;
        const float bb0 = bias[c0], bb1 = bias[c0 + 1];
#pragma unroll
        for (int mi = 0; mi < 4; mi++) {
#pragma unroll
            for (int half = 0; half < 2; half++) {
                const int row = bm0 + wm * 64 + mi * 16 + (lane >> 2) + half * 8;
                const float v0 = fmaf(fmaxf(acc[mi][ni][half * 2 + 0] + bb0, 0.0f), sa, sh0);
                const float v1 = fmaf(fmaxf(acc[mi][ni][half * 2 + 1] + bb1, 0.0f), sb, sh1);
                if (OUT_HALF) {
                    *(__half2*)(Ch + (size_t)row * HID + c0) = __floats2half2_rn(v0, v1);
                } else {
                    float2 o; o.x = v0; o.y = v1;
                    *(float2*)(Cf + (size_t)row * HID + c0) = o;
                }
            }
        }
    }
}

// ---------------------------------------------------------------------------
// Optional tail (pos_skip / batch_skip passthrough)
// ---------------------------------------------------------------------------
__global__ void tail_kernel(const float* __restrict__ pos_skip, float* __restrict__ out,
                            int has_pos, int has_batch) {
    const int i = blockIdx.x * blockDim.x + threadIdx.x;
    size_t off = (size_t)M_FINE * HID;
    if (has_pos) {
        if (i < M_FINE * 3) out[off + i] = pos_skip[i];
        off += (size_t)M_FINE * 3;
    }
    if (has_batch) {
        if (i < M_FINE) out[off + i] = (float)(i / NF);
    }
}

// ---------------------------------------------------------------------------
extern "C" void kernel_launch(void* const* d_in, const int* in_sizes, int n_in,
                              void* d_out, int out_size) {
    const float* x        = (const float*)d_in[0];
    const float* pos      = (const float*)d_in[1];
    const float* x_skip   = (const float*)d_in[3];
    const float* pos_skip = (const float*)d_in[4];
    const float* w1  = (const float*)d_in[6];
    const float* b1  = (const float*)d_in[7];
    const float* g1  = (const float*)d_in[8];
    const float* be1 = (const float*)d_in[9];
    const float* m1  = (const float*)d_in[10];
    const float* v1  = (const float*)d_in[11];
    const float* w2  = (const float*)d_in[12];
    const float* b2  = (const float*)d_in[13];
    const float* g2  = (const float*)d_in[14];
    const float* be2 = (const float*)d_in[15];
    const float* m2  = (const float*)d_in[16];
    const float* v2  = (const float*)d_in[17];
    float* out = (float*)d_out;

    static __half *xi = nullptr, *h1, *wt1, *wt2;
    if (!xi) {
        cudaGetSymbolAddress((void**)&xi, g_xi);
        cudaGetSymbolAddress((void**)&h1, g_h1);
        cudaGetSymbolAddress((void**)&wt1, g_wt1);
        cudaGetSymbolAddress((void**)&wt2, g_wt2);
        cudaFuncSetAttribute(gemm_mma<C0, 1>,  cudaFuncAttributeMaxDynamicSharedMemorySize, SMEM_GEMM);
        cudaFuncSetAttribute(gemm_mma<HID, 0>, cudaFuncAttributeMaxDynamicSharedMemorySize, SMEM_GEMM);
    }

    // 0) weight prep (tiled transpose + fp16 convert)
    wprep_kernel<<<W1_TILES + W2_TILES, 256>>>(w1, w2);
    // 1) kNN
    knn_kernel<<<dim3(BB, NF / 256), 256>>>(pos, pos_skip);
    // 2) interpolate + concat (fp16)
    gather_kernel<<<M_FINE, 128>>>(x, x_skip);
    // 3) MLP block 1: [M,384] @ [384,512] -> h1 (fp16)
    gemm_mma<C0, 1><<<dim3(HID / 256, M_FINE / 128), 512, SMEM_GEMM>>>(
        xi, wt1, b1, g1, be1, m1, v1, nullptr, h1);
    // 4) MLP block 2: [M,512] @ [512,512] -> d_out (fp32)
    gemm_mma<HID, 0><<<dim3(HID / 256, M_FINE / 128), 512, SMEM_GEMM>>>(
        h1, wt2, b2, g2, be2, m2, v2, out, nullptr);

    // 5) optional passthrough outputs
    const long extra = (long)out_size - (long)M_FINE * HID;
    if (extra > 0) {
        const int has_pos   = (extra >= (long)M_FINE * 3) ? 1 : 0;
        const long rem      = extra - (has_pos ? (long)M_FINE * 3 : 0);
        const int has_batch = (rem >= (long)M_FINE) ? 1 : 0;
        const int nmax = has_pos ? M_FINE * 3 : M_FINE;
        tail_kernel<<<(nmax + 255) / 256, 256>>>(pos_skip, out, has_pos, has_batch);
    }
}

// round 17
// speedup vs baseline: 1.1054x; 1.0401x over previous
#include <cuda_runtime.h>
#include <cuda_fp16.h>
#include <cstdint>

// Problem constants
#define BB      16
#define NC      1024
#define NF      4096
#define M_FINE  (BB * NF)       // 65536
#define CIN     256
#define CSKIP   128
#define C0      384
#define HID     512

// ---------------------------------------------------------------------------
// Device scratch (no cudaMalloc allowed)
// ---------------------------------------------------------------------------
__device__ __half g_xi[(size_t)M_FINE * C0];     // fp16 activations (layer-1 input)
__device__ __half g_h1[(size_t)M_FINE * HID];    // fp16 hidden (layer-2 input)
__device__ __half g_wt1[HID * C0];               // [n][k] = w1[k][n], fp16
__device__ __half g_wt2[HID * HID];
__device__ int   g_knn_idx[M_FINE * 3];
__device__ float g_knn_w[M_FINE * 3];

// ---------------------------------------------------------------------------
// Baseline-ISA tensor-core helpers (valid in compute_103 PTX)
// ---------------------------------------------------------------------------
__device__ __forceinline__ uint32_t smem_to_u32(const void* p) {
    uint32_t a;
    asm("{ .reg .u64 t; cvta.to.shared.u64 t, %1; cvt.u32.u64 %0, t; }" : "=r"(a) : "l"(p));
    return a;
}
__device__ __forceinline__ void cp_async16(uint32_t saddr, const void* gaddr) {
    asm volatile("cp.async.cg.shared.global [%0], [%1], 16;" :: "r"(saddr), "l"(gaddr));
}
#define CP_COMMIT() asm volatile("cp.async.commit_group;" ::: "memory")
#define CP_WAIT(N)  asm volatile("cp.async.wait_group %0;" :: "n"(N) : "memory")

__device__ __forceinline__ void ldsm_x4(uint32_t* r, uint32_t addr) {
    asm volatile("ldmatrix.sync.aligned.m8n8.x4.shared.b16 {%0,%1,%2,%3}, [%4];"
                 : "=r"(r[0]), "=r"(r[1]), "=r"(r[2]), "=r"(r[3]) : "r"(addr));
}
__device__ __forceinline__ void mma_fp16(float* c, const uint32_t* a, const uint32_t* b) {
    asm volatile("mma.sync.aligned.m16n8k16.row.col.f32.f16.f16.f32 "
                 "{%0,%1,%2,%3}, {%4,%5,%6,%7}, {%8,%9}, {%0,%1,%2,%3};"
                 : "+f"(c[0]), "+f"(c[1]), "+f"(c[2]), "+f"(c[3])
                 : "r"(a[0]), "r"(a[1]), "r"(a[2]), "r"(a[3]), "r"(b[0]), "r"(b[1]));
}

// ---------------------------------------------------------------------------
// Weight prep: smem-tiled transpose + fp16 convert (coalesced both ways)
// ---------------------------------------------------------------------------
#define W1_TILES ((C0 / 32) * (HID / 32))    // 192
#define W2_TILES ((HID / 32) * (HID / 32))   // 256
__global__ void wprep_kernel(const float* __restrict__ w1, const float* __restrict__ w2) {
    __shared__ float tile[32][33];
    int bt = blockIdx.x;
    const float* w;
    __half* dh;
    int KD;
    if (bt < W1_TILES) { w = w1; dh = g_wt1; KD = C0; }
    else { bt -= W1_TILES; w = w2; dh = g_wt2; KD = HID; }
    const int tk = bt / (HID / 32);
    const int tn = bt % (HID / 32);
    const int c  = threadIdx.x & 31;
    const int r0 = threadIdx.x >> 5;      // 0..7
#pragma unroll
    for (int rr = 0; rr < 32; rr += 8)
        tile[r0 + rr][c] = w[(size_t)(tk * 32 + r0 + rr) * HID + tn * 32 + c];
    __syncthreads();
#pragma unroll
    for (int rr = 0; rr < 32; rr += 8) {
        const int n = tn * 32 + r0 + rr;
        const int k = tk * 32 + c;
        dh[(size_t)n * KD + k] = __float2half(tile[c][r0 + rr]);   // = w[k][n]
    }
}

// ---------------------------------------------------------------------------
// Kernel 1: brute-force kNN (K=3)
// ---------------------------------------------------------------------------
__global__ void knn_kernel(const float* __restrict__ pos,
                           const float* __restrict__ pos_skip) {
    __shared__ float sp[NC * 3];
    const int b = blockIdx.x;
    const float* pbase = pos + (size_t)b * NC * 3;
    for (int i = threadIdx.x; i < NC * 3; i += blockDim.x) sp[i] = pbase[i];
    __syncthreads();

    const int p = b * NF + blockIdx.y * blockDim.x + threadIdx.x;
    const float qx = pos_skip[(size_t)p * 3 + 0];
    const float qy = pos_skip[(size_t)p * 3 + 1];
    const float qz = pos_skip[(size_t)p * 3 + 2];

    float d0 = 1e30f, d1 = 1e30f, d2 = 1e30f;
    int   i0 = 0,     i1 = 0,     i2 = 0;
#pragma unroll 4
    for (int j = 0; j < NC; j++) {
        const float dx = qx - sp[j * 3 + 0];
        const float dy = qy - sp[j * 3 + 1];
        const float dz = qz - sp[j * 3 + 2];
        const float d  = dx * dx + dy * dy + dz * dz;
        if (d < d2) {
            if (d < d1) {
                d2 = d1; i2 = i1;
                if (d < d0) { d1 = d0; i1 = i0; d0 = d; i0 = j; }
                else        { d1 = d;  i1 = j; }
            } else { d2 = d; i2 = j; }
        }
    }
    const float w0 = 1.0f / fmaxf(d0, 1e-16f);
    const float w1 = 1.0f / fmaxf(d1, 1e-16f);
    const float w2 = 1.0f / fmaxf(d2, 1e-16f);
    const float inv = 1.0f / (w0 + w1 + w2);
    g_knn_idx[p * 3 + 0] = b * NC + i0;
    g_knn_idx[p * 3 + 1] = b * NC + i1;
    g_knn_idx[p * 3 + 2] = b * NC + i2;
    g_knn_w  [p * 3 + 0] = w0 * inv;
    g_knn_w  [p * 3 + 1] = w1 * inv;
    g_knn_w  [p * 3 + 2] = w2 * inv;
}

// ---------------------------------------------------------------------------
// Kernel 2: gather + interpolate + concat -> fp16 [M, 384]
// Warp-per-point: 8 points per 256-thread block (8192 blocks total).
// Metadata loads are warp-broadcast; traffic coalescing unchanged.
// ---------------------------------------------------------------------------
__global__ void gather_kernel(const float* __restrict__ x,
                              const float* __restrict__ x_skip) {
    const int warp = threadIdx.x >> 5;   // 0..7
    const int lane = threadIdx.x & 31;
    const int p = blockIdx.x * 8 + warp;

    const int   i0 = g_knn_idx[p * 3 + 0];
    const int   i1 = g_knn_idx[p * 3 + 1];
    const int   i2 = g_knn_idx[p * 3 + 2];
    const float w0 = g_knn_w[p * 3 + 0];
    const float w1 = g_knn_w[p * 3 + 1];
    const float w2 = g_knn_w[p * 3 + 2];

    const float2* r0 = (const float2*)(x + (size_t)i0 * CIN);
    const float2* r1 = (const float2*)(x + (size_t)i1 * CIN);
    const float2* r2 = (const float2*)(x + (size_t)i2 * CIN);
    __half* out = g_xi + (size_t)p * C0;

    // interpolated channels: 256 ch = 128 float2, 32 lanes x 4 iters
#pragma unroll
    for (int it = 0; it < 4; it++) {
        const int t = it * 32 + lane;
        const float2 a = r0[t], b = r1[t], c = r2[t];
        const float v0 = w0 * a.x + w1 * b.x + w2 * c.x;
        const float v1 = w0 * a.y + w1 * b.y + w2 * c.y;
        *(__half2*)(out + 2 * t) = __floats2half2_rn(v0, v1);
    }
    // skip channels: 128 ch = 64 half2, 32 lanes x 2 iters
    const float2* sk = (const float2*)(x_skip + (size_t)p * CSKIP);
#pragma unroll
    for (int it = 0; it < 2; it++) {
        const int t = it * 32 + lane;
        const float2 s = sk[t];
        *(__half2*)(out + CIN + 2 * t) = __floats2half2_rn(s.x, s.y);
    }
}

// ---------------------------------------------------------------------------
// Kernel 3: fp16 HMMA GEMM, single-term fp16 weights.  (champion config)
// CTA tile 128x256, 512 threads = 16 warps (2m x 8n), warp 64x32, K-step 64.
// 3-stage cp.async pipeline, ONE __syncthreads per K-tile.
// 144B-padded rows (conflict-free ldmatrix).
// Fused bias + ReLU + BN. OUT_HALF: emit fp16 for next layer.
// ---------------------------------------------------------------------------
#define RSTRIDE   144                         // 64 halves + 8 pad
#define A_TILE_B  (128 * RSTRIDE)             // 18432 B
#define W_TILE_B  (256 * RSTRIDE)             // 36864 B
#define STAGE_B   (A_TILE_B + W_TILE_B)       // 55296 B
#define NSTAGE    3
#define SMEM_GEMM (NSTAGE * STAGE_B)          // 165888 B -> 1 CTA/SM (16 warps)

template <int KD, int OUT_HALF>
__global__ void __launch_bounds__(512, 1)
gemm_mma(const __half* __restrict__ A, const __half* __restrict__ W,
         const float* __restrict__ bias, const float* __restrict__ gam,
         const float* __restrict__ bet,  const float* __restrict__ mu,
         const float* __restrict__ var,
         float* __restrict__ Cf, __half* __restrict__ Ch) {
    extern __shared__ char smem[];
    const uint32_t sbase = smem_to_u32(smem);
    const int tid  = threadIdx.x;
    const int wid  = tid >> 5, lane = tid & 31;
    const int wm   = wid >> 3;          // 0..1  (64-row slab)
    const int wn   = wid & 7;           // 0..7  (32-col slab)
    const int bm0  = blockIdx.y * 128;
    const int bn0  = blockIdx.x * 256;

    const int arow  = tid >> 2;                // 0..127
    const int aseg0 = (tid & 3) * 2;           // 0,2,4,6
    const int wrow  = tid >> 1;                // 0..255
    const int wseg0 = (tid & 1) * 4;           // 0 or 4

    auto load_stage = [&](int kt) {
        const int k0 = kt * 64;
        const uint32_t stg = sbase + (kt % NSTAGE) * STAGE_B;
        const size_t ga = (size_t)(bm0 + arow) * KD + k0 + aseg0 * 8;
        const uint32_t sa = arow * RSTRIDE + aseg0 * 16;
#pragma unroll
        for (int s = 0; s < 2; s++)
            cp_async16(stg + sa + s * 16, A + ga + s * 8);
        const size_t gw = (size_t)(bn0 + wrow) * KD + k0 + wseg0 * 8;
        const uint32_t sw = A_TILE_B + wrow * RSTRIDE + wseg0 * 16;
#pragma unroll
        for (int s = 0; s < 4; s++)
            cp_async16(stg + sw + s * 16, W + gw + s * 8);
    };

    float acc[4][4][4] = {};   // [mi][ni][frag]

    const uint32_t a_row  = wm * 64 + (lane & 15);
    const uint32_t a_colb = (lane >> 4) * 16;
    const uint32_t b_row  = wn * 32 + ((lane >> 4) << 3) + (lane & 7);
    const uint32_t b_colb = ((lane >> 3) & 1) * 16;

    load_stage(0); CP_COMMIT();
    load_stage(1); CP_COMMIT();

    constexpr int NT = KD / 64;
#pragma unroll 1
    for (int t = 0; t < NT; t++) {
        CP_WAIT(1);
        __syncthreads();                     // single barrier per K-tile
        if (t + 2 < NT) { load_stage(t + 2); CP_COMMIT(); }

        const uint32_t stg = sbase + (t % NSTAGE) * STAGE_B;
        const uint32_t a_base = stg;
        const uint32_t w_base = stg + A_TILE_B;

#pragma unroll
        for (int kf = 0; kf < 4; kf++) {
            uint32_t af[4][4], bf[2][4];
#pragma unroll
            for (int mi = 0; mi < 4; mi++)
                ldsm_x4(af[mi], a_base + (a_row + mi * 16) * RSTRIDE + kf * 32 + a_colb);
#pragma unroll
            for (int nb = 0; nb < 2; nb++)
                ldsm_x4(bf[nb], w_base + (b_row + nb * 16) * RSTRIDE + kf * 32 + b_colb);
#pragma unroll
            for (int mi = 0; mi < 4; mi++)
#pragma unroll
                for (int nb = 0; nb < 2; nb++) {
                    mma_fp16(acc[mi][2 * nb + 0], af[mi], bf[nb] + 0);
                    mma_fp16(acc[mi][2 * nb + 1], af[mi], bf[nb] + 2);
                }
        }
        // no trailing barrier: next iteration's barrier (after CP_WAIT) protects
        // stage reuse because loads are issued only after that barrier.
    }

    // ----- fused epilogue: bias -> ReLU -> BN -----
#pragma unroll
    for (int ni = 0; ni < 4; ni++) {
        const int c0 = bn0 + wn * 32 + ni * 8 + (lane & 3) * 2;
        const float sa = gam[c0]     * rsqrtf(var[c0]     + 1e-5f);
        const float sb = gam[c0 + 1] * rsqrtf(var[c0 + 1] + 1e-5f);
        const float sh0 = bet[c0]     - mu[c0]     * sa;
        const float sh1 = bet[c0 + 1] - mu[c0 + 1] * sb;
        const float bb0 = bias[c0], bb1 = bias[c0 + 1];
#pragma unroll
        for (int mi = 0; mi < 4; mi++) {
#pragma unroll
            for (int half = 0; half < 2; half++) {
                const int row = bm0 + wm * 64 + mi * 16 + (lane >> 2) + half * 8;
                const float v0 = fmaf(fmaxf(acc[mi][ni][half * 2 + 0] + bb0, 0.0f), sa, sh0);
                const float v1 = fmaf(fmaxf(acc[mi][ni][half * 2 + 1] + bb1, 0.0f), sb, sh1);
                if (OUT_HALF) {
                    *(__half2*)(Ch + (size_t)row * HID + c0) = __floats2half2_rn(v0, v1);
                } else {
                    float2 o; o.x = v0; o.y = v1;
                    *(float2*)(Cf + (size_t)row * HID + c0) = o;
                }
            }
        }
    }
}

// ---------------------------------------------------------------------------
// Optional tail (pos_skip / batch_skip passthrough)
// ---------------------------------------------------------------------------
__global__ void tail_kernel(const float* __restrict__ pos_skip, float* __restrict__ out,
                            int has_pos, int has_batch) {
    const int i = blockIdx.x * blockDim.x + threadIdx.x;
    size_t off = (size_t)M_FINE * HID;
    if (has_pos) {
        if (i < M_FINE * 3) out[off + i] = pos_skip[i];
        off += (size_t)M_FINE * 3;
    }
    if (has_batch) {
        if (i < M_FINE) out[off + i] = (float)(i / NF);
    }
}

// ---------------------------------------------------------------------------
extern "C" void kernel_launch(void* const* d_in, const int* in_sizes, int n_in,
                              void* d_out, int out_size) {
    const float* x        = (const float*)d_in[0];
    const float* pos      = (const float*)d_in[1];
    const float* x_skip   = (const float*)d_in[3];
    const float* pos_skip = (const float*)d_in[4];
    const float* w1  = (const float*)d_in[6];
    const float* b1  = (const float*)d_in[7];
    const float* g1  = (const float*)d_in[8];
    const float* be1 = (const float*)d_in[9];
    const float* m1  = (const float*)d_in[10];
    const float* v1  = (const float*)d_in[11];
    const float* w2  = (const float*)d_in[12];
    const float* b2  = (const float*)d_in[13];
    const float* g2  = (const float*)d_in[14];
    const float* be2 = (const float*)d_in[15];
    const float* m2  = (const float*)d_in[16];
    const float* v2  = (const float*)d_in[17];
    float* out = (float*)d_out;

    static __half *xi = nullptr, *h1, *wt1, *wt2;
    if (!xi) {
        cudaGetSymbolAddress((void**)&xi, g_xi);
        cudaGetSymbolAddress((void**)&h1, g_h1);
        cudaGetSymbolAddress((void**)&wt1, g_wt1);
        cudaGetSymbolAddress((void**)&wt2, g_wt2);
        cudaFuncSetAttribute(gemm_mma<C0, 1>,  cudaFuncAttributeMaxDynamicSharedMemorySize, SMEM_GEMM);
        cudaFuncSetAttribute(gemm_mma<HID, 0>, cudaFuncAttributeMaxDynamicSharedMemorySize, SMEM_GEMM);
    }

    // 0) weight prep (tiled transpose + fp16 convert)
    wprep_kernel<<<W1_TILES + W2_TILES, 256>>>(w1, w2);
    // 1) kNN
    knn_kernel<<<dim3(BB, NF / 256), 256>>>(pos, pos_skip);
    // 2) interpolate + concat (fp16), warp-per-point
    gather_kernel<<<M_FINE / 8, 256>>>(x, x_skip);
    // 3) MLP block 1: [M,384] @ [384,512] -> h1 (fp16)
    gemm_mma<C0, 1><<<dim3(HID / 256, M_FINE / 128), 512, SMEM_GEMM>>>(
        xi, wt1, b1, g1, be1, m1, v1, nullptr, h1);
    // 4) MLP block 2: [M,512] @ [512,512] -> d_out (fp32)
    gemm_mma<HID, 0><<<dim3(HID / 256, M_FINE / 128), 512, SMEM_GEMM>>>(
        h1, wt2, b2, g2, be2, m2, v2, out, nullptr);

    // 5) optional passthrough outputs
    const long extra = (long)out_size - (long)M_FINE * HID;
    if (extra > 0) {
        const int has_pos   = (extra >= (long)M_FINE * 3) ? 1 : 0;
        const long rem      = extra - (has_pos ? (long)M_FINE * 3 : 0);
        const int has_batch = (rem >= (long)M_FINE) ? 1 : 0;
        const int nmax = has_pos ? M_FINE * 3 : M_FINE;
        tail_kernel<<<(nmax + 255) / 256, 256>>>(pos_skip, out, has_pos, has_batch);
    }
}